// round 4
// baseline (speedup 1.0000x reference)
#include <cuda_runtime.h>
#include <cstdint>
#include <math_constants.h>

#define NN   1024     // N (square)
#define BB   128      // batch
#define SPLITK 8
#define KS   (NN / SPLITK)   // 128 k per block
#define BK   32              // k chunk in smem
#define NCH  (KS / BK)       // 4 chunks
#define BM   64              // b tile per block
#define BN   64              // j tile per block
#define XS_STRIDE 68         // conflict-free padded stride
#define NTILES ((BB / BM) * (NN / BN))   // 32

// encoded-max accumulator: [BB][NN] = 0.5 MB. Zero == enc(-inf) by construction.
__device__ unsigned int g_enc[BB * NN];
// per-tile arrival counters (reset by the last block each launch)
__device__ unsigned int g_cnt[NTILES];

// Order-preserving fp32 -> uint32 encoding, shifted so enc(-inf) == 0.
// Standard enc: neg -> ~bits, pos -> bits | 0x80000000. enc(-inf) = 0x007FFFFF.
// Subtracting that offset cannot wrap for any finite/inf float, so order is kept.
__device__ __forceinline__ unsigned int enc_f32(float f) {
    unsigned int u = __float_as_uint(f);
    u = (u & 0x80000000u) ? ~u : (u | 0x80000000u);
    return u - 0x007FFFFFu;
}
__device__ __forceinline__ float dec_f32(unsigned int e) {
    unsigned int u = e + 0x007FFFFFu;
    return __uint_as_float((u & 0x80000000u) ? (u ^ 0x80000000u) : ~u);
}

__device__ __forceinline__ void cp_async16(uint32_t dst_smem, const void* src) {
    asm volatile("cp.async.cg.shared.global [%0], [%1], 16;\n"
                 :: "r"(dst_smem), "l"(src));
}
__device__ __forceinline__ void cp_commit() {
    asm volatile("cp.async.commit_group;\n" ::: "memory");
}
__device__ __forceinline__ void cp_wait0() {
    asm volatile("cp.async.wait_group 0;\n" ::: "memory");
}

__global__ void __launch_bounds__(256, 2)
tropical_fused(const float* __restrict__ x,
               const float* __restrict__ w,
               const float* __restrict__ bias,
               float* __restrict__ out)
{
    __shared__ float xs[2][BK][XS_STRIDE];  // x transposed: [k][b]
    __shared__ float ws[2][BK][BN];         // w natural:    [k][j]
    __shared__ unsigned int s_last;

    const int tid = threadIdx.x;
    const int tx  = tid & 15;        // j quad (0..15)
    const int ty  = tid >> 4;        // b quad (0..15)
    const int j0  = blockIdx.x * BN;
    const int b0  = blockIdx.y * BM;
    const int k0  = blockIdx.z * KS;
    const int tile = blockIdx.y * (NN / BN) + blockIdx.x;

    // x load mapping: 2 float4 per thread per chunk
    const int lb  = tid >> 3;              // 0..31 (+32 for second half)
    const int lf4 = (tid & 7) << 2;        // 0..28 step 4
    // w load mapping: 2 cp.async per thread per chunk
    const int wk  = tid >> 4;              // 0..15 (+16)
    const int wj  = (tid & 15) << 2;       // 0..60

    float acc[4][4];
    #pragma unroll
    for (int r = 0; r < 4; r++)
        #pragma unroll
        for (int c = 0; c < 4; c++)
            acc[r][c] = -CUDART_INF_F;

    // ---- prologue: chunk 0 into buffer 0 ----
    {
        #pragma unroll
        for (int h = 0; h < 2; h++) {
            const int bb = lb + 32 * h;
            float4 xr = *reinterpret_cast<const float4*>(&x[(b0 + bb) * NN + k0 + lf4]);
            xs[0][lf4 + 0][bb] = xr.x;
            xs[0][lf4 + 1][bb] = xr.y;
            xs[0][lf4 + 2][bb] = xr.z;
            xs[0][lf4 + 3][bb] = xr.w;
            uint32_t d = (uint32_t)__cvta_generic_to_shared(&ws[0][wk + 16 * h][wj]);
            cp_async16(d, &w[(k0 + wk + 16 * h) * NN + j0 + wj]);
        }
        cp_commit();
        cp_wait0();
        __syncthreads();
    }

    int buf = 0;
    #pragma unroll 1
    for (int c = 0; c < NCH; c++) {
        float4 xn0, xn1;
        const bool more = (c + 1 < NCH);
        if (more) {
            const int kb = k0 + (c + 1) * BK;
            xn0 = *reinterpret_cast<const float4*>(&x[(b0 + lb) * NN + kb + lf4]);
            xn1 = *reinterpret_cast<const float4*>(&x[(b0 + lb + 32) * NN + kb + lf4]);
            #pragma unroll
            for (int h = 0; h < 2; h++) {
                uint32_t d = (uint32_t)__cvta_generic_to_shared(&ws[buf ^ 1][wk + 16 * h][wj]);
                cp_async16(d, &w[(kb + wk + 16 * h) * NN + j0 + wj]);
            }
            cp_commit();
        }

        #pragma unroll 16
        for (int k = 0; k < BK; k++) {
            float4 xv = *reinterpret_cast<const float4*>(&xs[buf][k][ty << 2]);
            float4 wv = *reinterpret_cast<const float4*>(&ws[buf][k][tx << 2]);
            float xr4[4] = {xv.x, xv.y, xv.z, xv.w};
            float wc4[4] = {wv.x, wv.y, wv.z, wv.w};
            #pragma unroll
            for (int r = 0; r < 4; r++)
                #pragma unroll
                for (int cc = 0; cc < 4; cc++)
                    acc[r][cc] = fmaxf(acc[r][cc], xr4[r] - wc4[cc]);
        }

        if (more) {
            xs[buf ^ 1][lf4 + 0][lb] = xn0.x;
            xs[buf ^ 1][lf4 + 1][lb] = xn0.y;
            xs[buf ^ 1][lf4 + 2][lb] = xn0.z;
            xs[buf ^ 1][lf4 + 3][lb] = xn0.w;
            xs[buf ^ 1][lf4 + 0][lb + 32] = xn1.x;
            xs[buf ^ 1][lf4 + 1][lb + 32] = xn1.y;
            xs[buf ^ 1][lf4 + 2][lb + 32] = xn1.z;
            xs[buf ^ 1][lf4 + 3][lb + 32] = xn1.w;
            cp_wait0();
        }
        __syncthreads();
        buf ^= 1;
    }

    // ---- atomic-max partial epilogue (REDG, no return) ----
    #pragma unroll
    for (int r = 0; r < 4; r++) {
        unsigned int* row = &g_enc[(b0 + (ty << 2) + r) * NN + j0 + (tx << 2)];
        #pragma unroll
        for (int cc = 0; cc < 4; cc++)
            atomicMax(&row[cc], enc_f32(acc[r][cc]));
    }

    // ---- last block of this tile finalizes ----
    __threadfence();          // publish REDs before counter bump
    __syncthreads();
    if (tid == 0)
        s_last = (atomicAdd(&g_cnt[tile], 1u) == SPLITK - 1);
    __syncthreads();
    if (!s_last) return;
    __threadfence();          // acquire side

    // 4096 outputs / 256 threads = 16 per thread (4 uint4 groups)
    const int row = tid >> 2;             // 0..63
    const int cb  = (tid & 3) << 4;       // 0,16,32,48
    const uint4 zero4 = make_uint4(0, 0, 0, 0);
    #pragma unroll
    for (int q = 0; q < 4; q++) {
        const int col = cb + (q << 2);
        const int gidx = (b0 + row) * NN + j0 + col;
        uint4 e = __ldcg(reinterpret_cast<const uint4*>(&g_enc[gidx]));
        float4 bv = *reinterpret_cast<const float4*>(&bias[j0 + col]);
        float4 o;
        o.x = dec_f32(e.x) + bv.x;
        o.y = dec_f32(e.y) + bv.y;
        o.z = dec_f32(e.z) + bv.z;
        o.w = dec_f32(e.w) + bv.w;
        *reinterpret_cast<float4*>(&out[gidx]) = o;
        // reset scratch for the next graph replay
        *reinterpret_cast<uint4*>(&g_enc[gidx]) = zero4;
    }
    if (tid == 0)
        g_cnt[tile] = 0;      // reset counter for next replay
}

extern "C" void kernel_launch(void* const* d_in, const int* in_sizes, int n_in,
                              void* d_out, int out_size) {
    const float* x    = (const float*)d_in[0];   // [128, 1024]
    const float* wgt  = (const float*)d_in[1];   // [1024, 1024]
    const float* bias = (const float*)d_in[2];   // [1024]
    float* out = (float*)d_out;                  // [128, 1024]

    dim3 grid(NN / BN, BB / BM, SPLITK);         // (16, 2, 8) = 256 blocks
    tropical_fused<<<grid, 256>>>(x, wgt, bias, out);
}

// round 6
// speedup vs baseline: 1.3109x; 1.3109x over previous
#include <cuda_runtime.h>
#include <cstdint>
#include <math_constants.h>

#define NN   1024
#define BB   128
#define SPLITK 16
#define KS   (NN / SPLITK)   // 64 k per block
#define BK   32              // k chunk in smem
#define BM   64              // b tile
#define BN   128             // j tile
#define XS_STRIDE 68         // padded, 16B-aligned rows

// split-K partials: [SPLITK][BB][NN] = 8 MB
__device__ float g_partials[SPLITK * BB * NN];

__device__ __forceinline__ void cp_async16(uint32_t dst_smem, const void* src) {
    asm volatile("cp.async.cg.shared.global [%0], [%1], 16;\n"
                 :: "r"(dst_smem), "l"(src));
}
__device__ __forceinline__ void cp_commit() {
    asm volatile("cp.async.commit_group;\n" ::: "memory");
}
__device__ __forceinline__ void cp_wait0() {
    asm volatile("cp.async.wait_group 0;\n" ::: "memory");
}

__global__ void __launch_bounds__(256, 2)
tropical_main(const float* __restrict__ x,
              const float* __restrict__ w)
{
    __shared__ float xs[BK][XS_STRIDE];     // x transposed: [k][b]  (single buffer, 8.7KB)
    __shared__ float ws[2][BK][BN];         // w natural:    [k][j]  (double buffer, 32.8KB)

    const int tid = threadIdx.x;
    const int tx  = tid & 15;        // j group (0..15)
    const int ty  = tid >> 4;        // b quad  (0..15)
    const int j0  = blockIdx.x * BN;
    const int b0  = blockIdx.y * BM;
    const int k0  = blockIdx.z * KS;

    // x load mapping: 2 float4 per thread per chunk
    const int xb  = tid >> 3;              // 0..31 (+32)
    const int xk4 = (tid & 7) << 2;        // 0..28 step 4
    // ws load mapping: 4 cp16 per thread per chunk
    const int wrow = tid >> 5;             // 0..7 (+8h)
    const int wc4  = (tid & 31) << 2;      // 0..124 step 4

    float acc[4][8];
    #pragma unroll
    for (int r = 0; r < 4; r++)
        #pragma unroll
        for (int c = 0; c < 8; c++)
            acc[r][c] = -CUDART_INF_F;

    // ---- prologue: chunk 0 -> xs + ws[0] ----
    {
        #pragma unroll
        for (int h = 0; h < 2; h++) {
            const int bb = xb + 32 * h;
            float4 xr = *reinterpret_cast<const float4*>(&x[(b0 + bb) * NN + k0 + xk4]);
            xs[xk4 + 0][bb] = xr.x;
            xs[xk4 + 1][bb] = xr.y;
            xs[xk4 + 2][bb] = xr.z;
            xs[xk4 + 3][bb] = xr.w;
        }
        #pragma unroll
        for (int h = 0; h < 4; h++) {
            const int kr = wrow + 8 * h;
            uint32_t d = (uint32_t)__cvta_generic_to_shared(&ws[0][kr][wc4]);
            cp_async16(d, &w[(k0 + kr) * NN + j0 + wc4]);
        }
        cp_commit();
        cp_wait0();
        __syncthreads();
    }

    // ---- prefetch chunk 1: x into registers, ws via cp.async ----
    float4 xn0, xn1;
    {
        const int kb = k0 + BK;
        xn0 = *reinterpret_cast<const float4*>(&x[(b0 + xb) * NN + kb + xk4]);
        xn1 = *reinterpret_cast<const float4*>(&x[(b0 + xb + 32) * NN + kb + xk4]);
        #pragma unroll
        for (int h = 0; h < 4; h++) {
            const int kr = wrow + 8 * h;
            uint32_t d = (uint32_t)__cvta_generic_to_shared(&ws[1][kr][wc4]);
            cp_async16(d, &w[(kb + kr) * NN + j0 + wc4]);
        }
        cp_commit();
    }

    const int jq = tx << 2;   // 0..60 step 4

    // ---- compute chunk 0 ----
    #pragma unroll 16
    for (int k = 0; k < BK; k++) {
        float4 xv = *reinterpret_cast<const float4*>(&xs[k][ty << 2]);
        float4 w0 = *reinterpret_cast<const float4*>(&ws[0][k][jq]);
        float4 w1 = *reinterpret_cast<const float4*>(&ws[0][k][64 + jq]);
        float xr4[4] = {xv.x, xv.y, xv.z, xv.w};
        float wl[8]  = {w0.x, w0.y, w0.z, w0.w, w1.x, w1.y, w1.z, w1.w};
        #pragma unroll
        for (int r = 0; r < 4; r++)
            #pragma unroll
            for (int c = 0; c < 8; c++)
                acc[r][c] = fmaxf(acc[r][c], xr4[r] - wl[c]);
    }

    // ---- drain readers, then overwrite xs with chunk 1 ----
    __syncthreads();
    xs[xk4 + 0][xb] = xn0.x;
    xs[xk4 + 1][xb] = xn0.y;
    xs[xk4 + 2][xb] = xn0.z;
    xs[xk4 + 3][xb] = xn0.w;
    xs[xk4 + 0][xb + 32] = xn1.x;
    xs[xk4 + 1][xb + 32] = xn1.y;
    xs[xk4 + 2][xb + 32] = xn1.z;
    xs[xk4 + 3][xb + 32] = xn1.w;
    cp_wait0();
    __syncthreads();

    // ---- compute chunk 1 ----
    #pragma unroll 16
    for (int k = 0; k < BK; k++) {
        float4 xv = *reinterpret_cast<const float4*>(&xs[k][ty << 2]);
        float4 w0 = *reinterpret_cast<const float4*>(&ws[1][k][jq]);
        float4 w1 = *reinterpret_cast<const float4*>(&ws[1][k][64 + jq]);
        float xr4[4] = {xv.x, xv.y, xv.z, xv.w};
        float wl[8]  = {w0.x, w0.y, w0.z, w0.w, w1.x, w1.y, w1.z, w1.w};
        #pragma unroll
        for (int r = 0; r < 4; r++)
            #pragma unroll
            for (int c = 0; c < 8; c++)
                acc[r][c] = fmaxf(acc[r][c], xr4[r] - wl[c]);
    }

    // ---- write partials (plain stores) ----
    float* p = &g_partials[blockIdx.z * (BB * NN)];
    #pragma unroll
    for (int r = 0; r < 4; r++) {
        const int row = (b0 + (ty << 2) + r) * NN + j0;
        float4 o0, o1;
        o0.x = acc[r][0]; o0.y = acc[r][1]; o0.z = acc[r][2]; o0.w = acc[r][3];
        o1.x = acc[r][4]; o1.y = acc[r][5]; o1.z = acc[r][6]; o1.w = acc[r][7];
        *reinterpret_cast<float4*>(&p[row + jq])      = o0;
        *reinterpret_cast<float4*>(&p[row + 64 + jq]) = o1;
    }
}

__global__ void __launch_bounds__(256, 4)
tropical_reduce(const float* __restrict__ bias,
                float* __restrict__ out)
{
    const int i = (blockIdx.x * 256 + threadIdx.x) << 2;
    float4 m = *reinterpret_cast<const float4*>(&g_partials[i]);
    #pragma unroll
    for (int s = 1; s < SPLITK; s++) {
        float4 q = *reinterpret_cast<const float4*>(&g_partials[s * (BB * NN) + i]);
        m.x = fmaxf(m.x, q.x);
        m.y = fmaxf(m.y, q.y);
        m.z = fmaxf(m.z, q.z);
        m.w = fmaxf(m.w, q.w);
    }
    const int j = i & (NN - 1);
    float4 bv = *reinterpret_cast<const float4*>(&bias[j]);
    float4 o;
    o.x = m.x + bv.x;
    o.y = m.y + bv.y;
    o.z = m.z + bv.z;
    o.w = m.w + bv.w;
    *reinterpret_cast<float4*>(&out[i]) = o;
}

extern "C" void kernel_launch(void* const* d_in, const int* in_sizes, int n_in,
                              void* d_out, int out_size) {
    const float* x    = (const float*)d_in[0];   // [128, 1024]
    const float* wgt  = (const float*)d_in[1];   // [1024, 1024]
    const float* bias = (const float*)d_in[2];   // [1024]
    float* out = (float*)d_out;                  // [128, 1024]

    dim3 grid(NN / BN, BB / BM, SPLITK);         // (8, 2, 16) = 256 blocks
    tropical_main<<<grid, 256>>>(x, wgt);

    const int total = BB * NN;                   // 131072
    tropical_reduce<<<total / 4 / 256, 256>>>(bias, out);
}